// round 1
// baseline (speedup 1.0000x reference)
#include <cuda_runtime.h>
#include <math.h>

// Problem constants
#define Bb 2
#define Ss 4096
#define INs 2048
#define STATEs 2048
#define OUTs 2048
#define Hh 16
#define Dd 128
#define CHs 6144               // 3*STATE
#define FACTOR_ 0.0214373219f  // 1/sqrt(2048+128)

// ---------------- scratch (device globals: allocation-free) ----------------
__device__ float g_z [(size_t)Bb * Ss * CHs];   // after GEMM1+tanh
__device__ float g_zc[(size_t)Bb * Ss * CHs];   // after conv
__device__ float g_y [(size_t)Bb * Ss * STATEs];// scan output

// ---------------- math helpers ----------------
__device__ __forceinline__ float fast_tanh(float x) {
    float e = __expf(2.0f * x);
    return 1.0f - 2.0f / (e + 1.0f);   // safe at +-inf
}
__device__ __forceinline__ float fast_sigmoid(float x) {
    return 1.0f / (1.0f + __expf(-x));
}

// ---------------- GEMM: C[M,N] = A[M,K] * Bm[N,K]^T (+bias)(tanh) ----------
// 128x128 tile, 256 threads, 8x8 microtile, KT=16, register prefetch.
template<bool TANH, bool BIAS>
__global__ void __launch_bounds__(256)
gru_gemm_tn(const float* __restrict__ A, const float* __restrict__ Bm,
            const float* __restrict__ bias, float* __restrict__ C,
            int M, int N, int K)
{
    __shared__ float As[16][132];
    __shared__ float Bs[16][132];

    const int tid = threadIdx.x;
    const int tx  = tid & 15;       // 0..15 (cols)
    const int ty  = tid >> 4;       // 0..15 (rows)
    const int bm  = blockIdx.y << 7;
    const int bn  = blockIdx.x << 7;
    const int lr  = tid >> 2;       // 0..63
    const int lc  = (tid & 3) << 2; // 0,4,8,12

    const float* Ap = A  + (size_t)(bm + lr) * K + lc;
    const float* Bp = Bm + (size_t)(bn + lr) * K + lc;
    const size_t strideA = (size_t)64 * K;

    float acc[8][8];
#pragma unroll
    for (int i = 0; i < 8; i++)
#pragma unroll
        for (int j = 0; j < 8; j++) acc[i][j] = 0.0f;

    // prologue: prefetch first K-slab into registers
    float4 a0 = *(const float4*)(Ap);
    float4 a1 = *(const float4*)(Ap + strideA);
    float4 b0 = *(const float4*)(Bp);
    float4 b1 = *(const float4*)(Bp + strideA);

    for (int k0 = 0; k0 < K; k0 += 16) {
        __syncthreads();
        As[lc+0][lr]    = a0.x; As[lc+1][lr]    = a0.y; As[lc+2][lr]    = a0.z; As[lc+3][lr]    = a0.w;
        As[lc+0][lr+64] = a1.x; As[lc+1][lr+64] = a1.y; As[lc+2][lr+64] = a1.z; As[lc+3][lr+64] = a1.w;
        Bs[lc+0][lr]    = b0.x; Bs[lc+1][lr]    = b0.y; Bs[lc+2][lr]    = b0.z; Bs[lc+3][lr]    = b0.w;
        Bs[lc+0][lr+64] = b1.x; Bs[lc+1][lr+64] = b1.y; Bs[lc+2][lr+64] = b1.z; Bs[lc+3][lr+64] = b1.w;
        __syncthreads();

        if (k0 + 16 < K) {  // prefetch next slab (latency hidden under FMA block)
            a0 = *(const float4*)(Ap + k0 + 16);
            a1 = *(const float4*)(Ap + strideA + k0 + 16);
            b0 = *(const float4*)(Bp + k0 + 16);
            b1 = *(const float4*)(Bp + strideA + k0 + 16);
        }

#pragma unroll
        for (int kk = 0; kk < 16; kk++) {
            float4 av0 = *(const float4*)&As[kk][(ty << 2)];
            float4 av1 = *(const float4*)&As[kk][(ty << 2) + 64];
            float4 bv0 = *(const float4*)&Bs[kk][(tx << 2)];
            float4 bv1 = *(const float4*)&Bs[kk][(tx << 2) + 64];
            float av[8] = {av0.x, av0.y, av0.z, av0.w, av1.x, av1.y, av1.z, av1.w};
            float bv[8] = {bv0.x, bv0.y, bv0.z, bv0.w, bv1.x, bv1.y, bv1.z, bv1.w};
#pragma unroll
            for (int i = 0; i < 8; i++)
#pragma unroll
                for (int j = 0; j < 8; j++)
                    acc[i][j] = fmaf(av[i], bv[j], acc[i][j]);
        }
    }

    float bl[8];
#pragma unroll
    for (int j = 0; j < 8; j++) bl[j] = 0.0f;
    if (BIAS) {
        float4 t0 = *(const float4*)(bias + bn + (tx << 2));
        float4 t1 = *(const float4*)(bias + bn + 64 + (tx << 2));
        bl[0]=t0.x; bl[1]=t0.y; bl[2]=t0.z; bl[3]=t0.w;
        bl[4]=t1.x; bl[5]=t1.y; bl[6]=t1.z; bl[7]=t1.w;
    }

#pragma unroll
    for (int i = 0; i < 8; i++) {
        int row = bm + ((i < 4) ? ((ty << 2) + i) : (64 + (ty << 2) + (i - 4)));
        float o[8];
#pragma unroll
        for (int j = 0; j < 8; j++) {
            float v = acc[i][j] + bl[j];
            if (TANH) v = fast_tanh(v);
            o[j] = v;
        }
        float* Cp = C + (size_t)row * N + bn;
        *(float4*)(Cp + (tx << 2))      = make_float4(o[0], o[1], o[2], o[3]);
        *(float4*)(Cp + 64 + (tx << 2)) = make_float4(o[4], o[5], o[6], o[7]);
    }
}

// ---------------- depthwise causal conv (K=4) + bias, * FACTOR -------------
// out[b,s,c] = (w0*z[s-3] + w1*z[s-2] + w2*z[s-1] + w3*z[s] + cb[c]) * FACTOR
__global__ void __launch_bounds__(256)
gru_conv(const float* __restrict__ z, const float* __restrict__ cw,
         const float* __restrict__ cb, float* __restrict__ out)
{
    const int c  = blockIdx.x * 256 + threadIdx.x;     // 0..6143
    const int s0 = blockIdx.y * 256;                   // chunk of 256 steps
    const int b  = blockIdx.z;

    const float w0 = cw[c * 4 + 0];
    const float w1 = cw[c * 4 + 1];
    const float w2 = cw[c * 4 + 2];
    const float w3 = cw[c * 4 + 3];
    const float bi = cb[c];

    const float* zp = z   + (size_t)b * Ss * CHs + c;
    float*       op = out + (size_t)b * Ss * CHs + c;

    float x0 = (s0 >= 3) ? zp[(size_t)(s0 - 3) * CHs] : 0.0f;
    float x1 = (s0 >= 2) ? zp[(size_t)(s0 - 2) * CHs] : 0.0f;
    float x2 = (s0 >= 1) ? zp[(size_t)(s0 - 1) * CHs] : 0.0f;

    for (int s = s0; s < s0 + 256; s++) {
        float x3 = zp[(size_t)s * CHs];
        float r  = w0 * x0 + w1 * x1 + w2 * x2 + w3 * x3;
        op[(size_t)s * CHs] = (r + bi) * FACTOR_;
        x0 = x1; x1 = x2; x2 = x3;
    }
}

// ---------------- GRU scan: one CTA per (b,h), weights in SMEM -------------
// grid = 32 (b*16+h), 256 threads: e = tid&127 output column, half = tid>>7
// splits the d-reduction in two. Weights (x FACTOR) resident in dynamic SMEM.
__global__ void __launch_bounds__(256)
gru_scan(const float* __restrict__ zc, const float* __restrict__ sw,
         float* __restrict__ y)
{
    extern __shared__ float sm[];
    float* w_s  = sm;            // 16384 floats: cand weights [d][e]
    float* fw_s = sm + 16384;    // forget
    float* rw_s = sm + 32768;    // reset
    float* h_s  = sm + 49152;    // 128
    float* rh_s = h_s  + 128;    // 128
    float* f_s  = rh_s + 128;    // 128
    float* pr   = f_s  + 128;    // 256
    float* pf   = pr   + 256;    // 256
    float* pc   = pf   + 256;    // 256

    const int tid  = threadIdx.x;
    const int b    = blockIdx.x >> 4;
    const int h    = blockIdx.x & 15;
    const int e    = tid & 127;
    const int half = tid >> 7;
    const int d0   = half * 64;

    // load weights for this head, scaled by FACTOR
    const float* wg0 = sw + (size_t)(h)      * Dd * Dd;  // w (cand)
    const float* wg1 = sw + (size_t)(16 + h) * Dd * Dd;  // fw
    const float* wg2 = sw + (size_t)(32 + h) * Dd * Dd;  // rw
    for (int i = tid * 4; i < Dd * Dd; i += 1024) {
        float4 v;
        v = *(const float4*)(wg0 + i);
        v.x *= FACTOR_; v.y *= FACTOR_; v.z *= FACTOR_; v.w *= FACTOR_;
        *(float4*)(w_s + i) = v;
        v = *(const float4*)(wg1 + i);
        v.x *= FACTOR_; v.y *= FACTOR_; v.z *= FACTOR_; v.w *= FACTOR_;
        *(float4*)(fw_s + i) = v;
        v = *(const float4*)(wg2 + i);
        v.x *= FACTOR_; v.y *= FACTOR_; v.z *= FACTOR_; v.w *= FACTOR_;
        *(float4*)(rw_s + i) = v;
    }
    if (tid < 128) h_s[tid] = 0.0f;
    __syncthreads();

    const float* zb  = zc + (size_t)b * Ss * CHs;
    float*       yb  = y  + (size_t)b * Ss * STATEs;
    const int    col = h * 128 + e;

    // preload gate inputs for s=0 (finalizer half only)
    float iin = 0.0f, fin = 0.0f, rin = 0.0f;
    if (!half) {
        iin = zb[col];
        fin = zb[2048 + col];
        rin = zb[4096 + col];
    }

    for (int s = 0; s < Ss; s++) {
        // prefetch next step's gate inputs (overlaps with matvec compute)
        float ni = 0.0f, nf = 0.0f, nr = 0.0f;
        if (!half && (s + 1) < Ss) {
            const float* zs = zb + (size_t)(s + 1) * CHs;
            ni = zs[col];
            nf = zs[2048 + col];
            nr = zs[4096 + col];
        }

        // phase 1: partial r/f matvecs over d in [d0, d0+64)
        float ar0 = 0.f, ar1 = 0.f, af0 = 0.f, af1 = 0.f;
#pragma unroll
        for (int d = 0; d < 64; d += 4) {
            float4 h4 = *(const float4*)(h_s + d0 + d);
            const float* rp = rw_s + (d0 + d) * 128 + e;
            const float* fp = fw_s + (d0 + d) * 128 + e;
            ar0 = fmaf(h4.x, rp[0],   ar0);
            af0 = fmaf(h4.x, fp[0],   af0);
            ar1 = fmaf(h4.y, rp[128], ar1);
            af1 = fmaf(h4.y, fp[128], af1);
            ar0 = fmaf(h4.z, rp[256], ar0);
            af0 = fmaf(h4.z, fp[256], af0);
            ar1 = fmaf(h4.w, rp[384], ar1);
            af1 = fmaf(h4.w, fp[384], af1);
        }
        pr[tid] = ar0 + ar1;
        pf[tid] = af0 + af1;
        __syncthreads();

        if (!half) {
            float r = fast_sigmoid(rin + pr[e] + pr[128 + e]);
            float f = fast_sigmoid(fin + pf[e] + pf[128 + e]);
            rh_s[e] = r * h_s[e];
            f_s[e]  = f;
        }
        __syncthreads();

        // phase 2: partial cand matvec on (r*h)
        float ac0 = 0.f, ac1 = 0.f;
#pragma unroll
        for (int d = 0; d < 64; d += 4) {
            float4 r4 = *(const float4*)(rh_s + d0 + d);
            const float* wp = w_s + (d0 + d) * 128 + e;
            ac0 = fmaf(r4.x, wp[0],   ac0);
            ac1 = fmaf(r4.y, wp[128], ac1);
            ac0 = fmaf(r4.z, wp[256], ac0);
            ac1 = fmaf(r4.w, wp[384], ac1);
        }
        pc[tid] = ac0 + ac1;
        __syncthreads();

        if (!half) {
            float cand = fast_tanh(iin + pc[e] + pc[128 + e]);
            float f    = f_s[e];
            float hn   = fmaf(f, h_s[e] - cand, cand);  // f*h + (1-f)*cand
            h_s[e] = hn;
            yb[(size_t)s * STATEs + col] = hn;
        }
        iin = ni; fin = nf; rin = nr;
        __syncthreads();  // h_s visible before next phase 1
    }
}

// ---------------- launch ----------------
extern "C" void kernel_launch(void* const* d_in, const int* in_sizes, int n_in,
                              void* d_out, int out_size)
{
    const float* x    = (const float*)d_in[0];   // (B,S,IN)
    const float* w_in = (const float*)d_in[1];   // (3*STATE, IN)
    const float* b_in = (const float*)d_in[2];   // (3*STATE)
    const float* cw   = (const float*)d_in[3];   // (3*STATE,1,4)
    const float* cb   = (const float*)d_in[4];   // (3*STATE)
    const float* swt  = (const float*)d_in[5];   // (48,128,128)
    const float* wout = (const float*)d_in[6];   // (OUT, STATE)
    float* out = (float*)d_out;

    float *zp, *zcp, *yp;
    cudaGetSymbolAddress((void**)&zp,  g_z);
    cudaGetSymbolAddress((void**)&zcp, g_zc);
    cudaGetSymbolAddress((void**)&yp,  g_y);

    // GEMM1: z = tanh(x @ w_in^T + b_in)   [8192 x 6144], K=2048
    {
        dim3 grid(CHs / 128, (Bb * Ss) / 128);
        gru_gemm_tn<true, true><<<grid, 256>>>(x, w_in, b_in, zp,
                                               Bb * Ss, CHs, INs);
    }
    // depthwise causal conv + bias, * FACTOR
    {
        dim3 grid(CHs / 256, Ss / 256, Bb);
        gru_conv<<<grid, 256>>>(zp, cw, cb, zcp);
    }
    // GRU scan
    {
        const int smem_bytes = (49152 + 3 * 128 + 3 * 256) * (int)sizeof(float);
        cudaFuncSetAttribute(gru_scan,
                             cudaFuncAttributeMaxDynamicSharedMemorySize,
                             smem_bytes);
        gru_scan<<<Bb * Hh, 256, smem_bytes>>>(zcp, swt, yp);
    }
    // GEMM2: out = y @ w_out^T   [8192 x 2048], K=2048
    {
        dim3 grid(OUTs / 128, (Bb * Ss) / 128);
        gru_gemm_tn<false, false><<<grid, 256>>>(yp, wout, (const float*)0, out,
                                                 Bb * Ss, OUTs, STATEs);
    }
}